// round 12
// baseline (speedup 1.0000x reference)
#include <cuda_runtime.h>
#include <cuda_fp16.h>

// Problem constants: b=48, n=512, DIM=96, HEADS=6, hd=16, h=w=d=8
#define NB 48
#define NTOK 512
#define NHEAD 6
#define NPOS 43
#define L2E 1.4426950408889634f
#define QS (0.25f * L2E)     // attention scale folded with log2(e)

__device__ __half g_x1h[NB * NHEAD * NTOK * 16];   // pass-1 output (fp16)

// ---------------------------------------------------------------------------
// helpers
// ---------------------------------------------------------------------------
__device__ __forceinline__ unsigned pkh(float lo, float hi) {   // f16x2 {lo,hi}
    unsigned d; asm("cvt.rn.f16x2.f32 %0,%1,%2;" : "=r"(d) : "f"(hi), "f"(lo)); return d;
}
__device__ __forceinline__ unsigned hex2(unsigned x) {          // 2^x on f16x2
    unsigned r; asm("ex2.approx.f16x2 %0,%1;" : "=r"(r) : "r"(x)); return r;
}
// fp16 mma, fp32 accumulate in place
__device__ __forceinline__ void mma_f16(
    float& c0, float& c1, float& c2, float& c3,
    unsigned a0, unsigned a1, unsigned a2, unsigned a3,
    unsigned b0, unsigned b1)
{
    asm("mma.sync.aligned.m16n8k16.row.col.f32.f16.f16.f32 "
        "{%0,%1,%2,%3},{%4,%5,%6,%7},{%8,%9},{%0,%1,%2,%3};"
        : "+f"(c0), "+f"(c1), "+f"(c2), "+f"(c3)
        : "r"(a0), "r"(a1), "r"(a2), "r"(a3), "r"(b0), "r"(b1));
}
// fp16 mma, fp16 accumulator (C-in = packed bias, D = packed S+bias)
__device__ __forceinline__ void mma_f16h(
    unsigned& d0, unsigned& d1,
    unsigned a0, unsigned a1, unsigned a2, unsigned a3,
    unsigned b0, unsigned b1, unsigned c0, unsigned c1)
{
    asm("mma.sync.aligned.m16n8k16.row.col.f16.f16.f16.f16 "
        "{%0,%1},{%2,%3,%4,%5},{%6,%7},{%8,%9};"
        : "=r"(d0), "=r"(d1)
        : "r"(a0), "r"(a1), "r"(a2), "r"(a3), "r"(b0), "r"(b1),
          "r"(c0), "r"(c1));
}
__device__ __forceinline__ int ds9(int t) {   // base-8 digit sum, t < 512
    return (t >> 6) + ((t >> 3) & 7) + (t & 7);
}

// smem word offsets (4B words) — per kernel: one K + one V + tables
#define SKO 0
#define SVO 4096
#define SPO 8192
#define SBO 8240
#define SMEM_WORDS 8288

// ---------------------------------------------------------------------------
// pos-MLP single row -> bias value for (table i, row m, head h)
// ---------------------------------------------------------------------------
__device__ float pos_mlp_row(int i, int m, int h,
    const float* __restrict__ W0, const float* __restrict__ B0,
    const float* __restrict__ G1, const float* __restrict__ Be1,
    const float* __restrict__ W1, const float* __restrict__ B1,
    const float* __restrict__ G2, const float* __restrict__ Be2,
    const float* __restrict__ W2, const float* __restrict__ B2,
    const float* __restrict__ G3, const float* __restrict__ Be3,
    const float* __restrict__ W3, const float* __restrict__ B3)
{
    float bh_ = -7.f;
    float bw_ = (float)(m / 15) - 7.f;
    float bd_ = (float)(m % 15) - 7.f;
    float x[6], y[6];
#pragma unroll
    for (int j = 0; j < 6; ++j) {
        const float* w = W0 + (i * 6 + j) * 3;
        x[j] = bh_ * w[0] + bw_ * w[1] + bd_ * w[2] + B0[i * 6 + j];
    }
    {
        float mu = 0.f;
#pragma unroll
        for (int j = 0; j < 6; ++j) mu += x[j];
        mu *= (1.f / 6.f);
        float var = 0.f;
#pragma unroll
        for (int j = 0; j < 6; ++j) { float d = x[j] - mu; var += d * d; }
        float inv = rsqrtf(var * (1.f / 6.f) + 1e-5f);
#pragma unroll
        for (int j = 0; j < 6; ++j)
            x[j] = fmaxf((x[j] - mu) * inv * G1[i * 6 + j] + Be1[i * 6 + j], 0.f);
#pragma unroll
        for (int j = 0; j < 6; ++j) {
            const float* w = W1 + (i * 6 + j) * 6;
            float s = B1[i * 6 + j];
#pragma unroll
            for (int k = 0; k < 6; ++k) s += x[k] * w[k];
            y[j] = s;
        }
    }
    {
        float mu = 0.f;
#pragma unroll
        for (int j = 0; j < 6; ++j) mu += y[j];
        mu *= (1.f / 6.f);
        float var = 0.f;
#pragma unroll
        for (int j = 0; j < 6; ++j) { float d = y[j] - mu; var += d * d; }
        float inv = rsqrtf(var * (1.f / 6.f) + 1e-5f);
#pragma unroll
        for (int j = 0; j < 6; ++j)
            y[j] = fmaxf((y[j] - mu) * inv * G2[i * 6 + j] + Be2[i * 6 + j], 0.f);
#pragma unroll
        for (int j = 0; j < 6; ++j) {
            const float* w = W2 + (i * 6 + j) * 6;
            float s = B2[i * 6 + j];
#pragma unroll
            for (int k = 0; k < 6; ++k) s += y[k] * w[k];
            x[j] = s;
        }
    }
    {
        float mu = 0.f;
#pragma unroll
        for (int j = 0; j < 6; ++j) mu += x[j];
        mu *= (1.f / 6.f);
        float var = 0.f;
#pragma unroll
        for (int j = 0; j < 6; ++j) { float d = x[j] - mu; var += d * d; }
        float inv = rsqrtf(var * (1.f / 6.f) + 1e-5f);
#pragma unroll
        for (int j = 0; j < 6; ++j)
            x[j] = fmaxf((x[j] - mu) * inv * G3[i * 6 + j] + Be3[i * 6 + j], 0.f);
        const float* w = W3 + (i * NHEAD + h) * 6;
        float s = B3[i * NHEAD + h];
#pragma unroll
        for (int k = 0; k < 6; ++k) s += x[k] * w[k];
        return s;
    }
}

#define POSARGS W0, B0, G1, Be1, W1, B1, G2, Be2, W2, B2, G3, Be3, W3, B3
#define POSPARAMS const float* __restrict__ W0, const float* __restrict__ B0, \
    const float* __restrict__ G1, const float* __restrict__ Be1, \
    const float* __restrict__ W1, const float* __restrict__ B1, \
    const float* __restrict__ G2, const float* __restrict__ Be2, \
    const float* __restrict__ W2, const float* __restrict__ B2, \
    const float* __restrict__ G3, const float* __restrict__ Be3, \
    const float* __restrict__ W3, const float* __restrict__ B3

// ---------------------------------------------------------------------------
// attention core: 2 m-tiles (32 query rows per warp), 32 blocks of 16 keys.
// ---------------------------------------------------------------------------
__device__ __forceinline__ void attn_core2(
    const float* __restrict__ Qp, int qt,
    const unsigned* __restrict__ sK, const unsigned* __restrict__ sV,
    const unsigned* __restrict__ sB,
    int rowBase, int lane,
    float o[2][2][4], float oS[2][4])
{
    int lq = lane >> 2, lr = lane & 3;
    unsigned bsum = (lq == 0) ? 0x3C003C00u : 0u;   // ones column B-frag

    unsigned qa[2][4];
    int ib[2];
#pragma unroll
    for (int mt = 0; mt < 2; ++mt) {
        int r0 = rowBase + mt * 16 + lq;
        float2 qv0 = *(const float2*)(Qp + r0 * qt + 2 * lr);
        float2 qv1 = *(const float2*)(Qp + r0 * qt + 8 + 2 * lr);
        float2 qv2 = *(const float2*)(Qp + (r0 + 8) * qt + 2 * lr);
        float2 qv3 = *(const float2*)(Qp + (r0 + 8) * qt + 8 + 2 * lr);
        qa[mt][0] = pkh(qv0.x * QS, qv0.y * QS);
        qa[mt][1] = pkh(qv2.x * QS, qv2.y * QS);
        qa[mt][2] = pkh(qv1.x * QS, qv1.y * QS);
        qa[mt][3] = pkh(qv3.x * QS, qv3.y * QS);
        ib[mt] = ds9(r0) + 21 - 2 * lr;
#pragma unroll
        for (int nt = 0; nt < 2; ++nt)
#pragma unroll
            for (int j = 0; j < 4; ++j) o[mt][nt][j] = 0.f;
#pragma unroll
        for (int j = 0; j < 4; ++j) oS[mt][j] = 0.f;
    }

    for (int blk = 0; blk < 32; ++blk) {
        uint2 k0 = *(const uint2*)(sK + (blk * 2 + 0) * 64 + lane * 2);
        uint2 k1 = *(const uint2*)(sK + (blk * 2 + 1) * 64 + lane * 2);
        uint2 v0 = *(const uint2*)(sV + (blk * 2 + 0) * 64 + lane * 2);
        uint2 v1 = *(const uint2*)(sV + (blk * 2 + 1) * 64 + lane * 2);
        int dsb = (blk >> 2) + ((2 * blk) & 7);

#pragma unroll
        for (int mt = 0; mt < 2; ++mt) {
            int i0 = ib[mt] - dsb;
            unsigned b0 = sB[i0];
            unsigned bp = sB[i0 + 1];
            unsigned bm = sB[i0 - 1];

            unsigned e0, e1, f0, f1;
            mma_f16h(e0, e1, qa[mt][0], qa[mt][1], qa[mt][2], qa[mt][3],
                     k0.x, k0.y, b0, bp);
            mma_f16h(f0, f1, qa[mt][0], qa[mt][1], qa[mt][2], qa[mt][3],
                     k1.x, k1.y, bm, b0);

            unsigned a0 = hex2(e0);
            unsigned a1 = hex2(e1);
            unsigned a2 = hex2(f0);
            unsigned a3 = hex2(f1);

            mma_f16(o[mt][0][0], o[mt][0][1], o[mt][0][2], o[mt][0][3],
                    a0, a1, a2, a3, v0.x, v0.y);
            mma_f16(o[mt][1][0], o[mt][1][1], o[mt][1][2], o[mt][1][3],
                    a0, a1, a2, a3, v1.x, v1.y);
            mma_f16(oS[mt][0], oS[mt][1], oS[mt][2], oS[mt][3],
                    a0, a1, a2, a3, bsum, bsum);
        }
    }
}

// ---------------------------------------------------------------------------
// PASS 1 kernel: Q=grid, K=qkv.k, V=qkv.v -> g_x1h. 2 CTAs per (b,head).
// ---------------------------------------------------------------------------
__global__ __launch_bounds__(256, 3) void pass1_kernel(
    const float* __restrict__ qkv, const float* __restrict__ grid,
    POSPARAMS)
{
    extern __shared__ float sm[];
    unsigned* sK = (unsigned*)(sm + SKO);
    unsigned* sV = (unsigned*)(sm + SVO);
    float* sPos = sm + SPO;
    unsigned* sB = (unsigned*)(sm + SBO);

    int cta = blockIdx.x;
    int bh = cta >> 1, half = cta & 1;
    int b = bh / NHEAD, h = bh % NHEAD;
    const float* qkvB = qkv + (long)b * NTOK * 288;
    const float* gridB = grid + (long)b * NTOK * 96;

    int tid = threadIdx.x;

    for (int e = tid; e < NTOK * 4; e += 256) {
        int key = e >> 2;
        int c4 = (e & 3) * 4;
        float4 kv = *(const float4*)(qkvB + key * 288 + 96 + h * 16 + c4);
        float4 vv = *(const float4*)(qkvB + key * 288 + 192 + h * 16 + c4);
        float kj[4] = { kv.x, kv.y, kv.z, kv.w };
        float vj[4] = { vv.x, vv.y, vv.z, vv.w };
        int blk = key >> 4, kl = key & 15;
        int ntK = kl >> 3, lqK = kl & 7;
#pragma unroll
        for (int jp = 0; jp < 2; ++jp) {
            int d = c4 + 2 * jp;
            int w = (blk * 2 + ntK) * 64 + lqK * 8 + ((d & 7) >> 1) * 2 + (d >> 3);
            sK[w] = pkh(kj[2 * jp], kj[2 * jp + 1]);
        }
        int lrV = (kl & 7) >> 1, regV = kl >> 3, hfV = kl & 1;
#pragma unroll
        for (int j = 0; j < 4; ++j) {
            int dim = c4 + j;
            int w = (blk * 2 + (dim >> 3)) * 64 + (dim & 7) * 8 + lrV * 2 + regV;
            ((__half*)sV)[w * 2 + hfV] = __float2half_rn(vj[j]);
        }
    }

    if (tid < NPOS)
        sPos[tid] = pos_mlp_row(0, tid, h, POSARGS) * L2E;
    __syncthreads();
    if (tid < 48) {
        float lo = (tid < NPOS) ? sPos[tid] : 0.f;
        float hi = (tid >= 1) ? sPos[tid - 1] : 0.f;
        sB[tid] = pkh(lo, hi);
    }
    __syncthreads();

    int warp = tid >> 5, lane = tid & 31, lq = lane >> 2, lr = lane & 3;
    int rowBase = half * 256 + warp * 32;

    float o[2][2][4], oS[2][4];
    attn_core2(gridB + h * 16, 96, sK, sV, sB, rowBase, lane, o, oS);

    unsigned* x1u = (unsigned*)g_x1h;
#pragma unroll
    for (int mt = 0; mt < 2; ++mt) {
        float sl = __shfl_sync(0xffffffffu, oS[mt][0], lane & ~3);
        float sh = __shfl_sync(0xffffffffu, oS[mt][2], lane & ~3);
        float il = 1.f / sl, ih = 1.f / sh;
        int r0 = rowBase + mt * 16 + lq, r1 = r0 + 8;
#pragma unroll
        for (int nt = 0; nt < 2; ++nt) {
            int col = nt * 8 + 2 * lr;
            x1u[(((bh * NTOK) + r0) * 16 + col) >> 1] = pkh(o[mt][nt][0] * il, o[mt][nt][1] * il);
            x1u[(((bh * NTOK) + r1) * 16 + col) >> 1] = pkh(o[mt][nt][2] * ih, o[mt][nt][3] * ih);
        }
    }
}

// ---------------------------------------------------------------------------
// PASS 2 kernel: Q=qkv.q, K=grid, V=g_x1h -> out. 2 CTAs per (b,head).
// ---------------------------------------------------------------------------
__global__ __launch_bounds__(256, 3) void pass2_kernel(
    const float* __restrict__ qkv, const float* __restrict__ grid,
    POSPARAMS, float* __restrict__ out)
{
    extern __shared__ float sm[];
    unsigned* sK = (unsigned*)(sm + SKO);
    unsigned* sV = (unsigned*)(sm + SVO);
    float* sPos = sm + SPO;
    unsigned* sB = (unsigned*)(sm + SBO);

    int cta = blockIdx.x;
    int bh = cta >> 1, half = cta & 1;
    int b = bh / NHEAD, h = bh % NHEAD;
    const float* qkvB = qkv + (long)b * NTOK * 288;
    const float* gridB = grid + (long)b * NTOK * 96;

    int tid = threadIdx.x;
    const unsigned* x1u = (const unsigned*)g_x1h;

    for (int e = tid; e < NTOK * 4; e += 256) {
        int key = e >> 2;
        int c4 = (e & 3) * 4;
        float4 gv = *(const float4*)(gridB + key * 96 + h * 16 + c4);
        float gj[4] = { gv.x, gv.y, gv.z, gv.w };
        int blk = key >> 4, kl = key & 15;
        int ntK = kl >> 3, lqK = kl & 7;
#pragma unroll
        for (int jp = 0; jp < 2; ++jp) {
            int d = c4 + 2 * jp;
            int w = (blk * 2 + ntK) * 64 + lqK * 8 + ((d & 7) >> 1) * 2 + (d >> 3);
            sK[w] = pkh(gj[2 * jp], gj[2 * jp + 1]);
        }
        // V from x1 (already fp16): 4 halves per iter
        uint2 u = *(const uint2*)(x1u + ((((bh * NTOK) + key) * 16 + c4) >> 1));
        unsigned short hs[4];
        hs[0] = (unsigned short)(u.x & 0xffffu);
        hs[1] = (unsigned short)(u.x >> 16);
        hs[2] = (unsigned short)(u.y & 0xffffu);
        hs[3] = (unsigned short)(u.y >> 16);
        int lrV = (kl & 7) >> 1, regV = kl >> 3, hfV = kl & 1;
#pragma unroll
        for (int j = 0; j < 4; ++j) {
            int dim = c4 + j;
            int w = (blk * 2 + (dim >> 3)) * 64 + (dim & 7) * 8 + lrV * 2 + regV;
            ((unsigned short*)sV)[w * 2 + hfV] = hs[j];
        }
    }

    if (tid < NPOS)
        sPos[tid] = pos_mlp_row(1, tid, h, POSARGS) * L2E;
    __syncthreads();
    if (tid < 48) {
        float lo = (tid < NPOS) ? sPos[tid] : 0.f;
        float hi = (tid >= 1) ? sPos[tid - 1] : 0.f;
        sB[tid] = pkh(lo, hi);
    }
    __syncthreads();

    int warp = tid >> 5, lane = tid & 31, lq = lane >> 2, lr = lane & 3;
    int rowBase = half * 256 + warp * 32;

    float o[2][2][4], oS[2][4];
    attn_core2(qkvB + h * 16, 288, sK, sV, sB, rowBase, lane, o, oS);

    float* O = out + (long)b * NTOK * 96 + h * 16;
#pragma unroll
    for (int mt = 0; mt < 2; ++mt) {
        float sl = __shfl_sync(0xffffffffu, oS[mt][0], lane & ~3);
        float sh = __shfl_sync(0xffffffffu, oS[mt][2], lane & ~3);
        float il = 1.f / sl, ih = 1.f / sh;
        int r0 = rowBase + mt * 16 + lq, r1 = r0 + 8;
#pragma unroll
        for (int nt = 0; nt < 2; ++nt) {
            int col = nt * 8 + 2 * lr;
            *(float2*)(O + r0 * 96 + col) = make_float2(o[mt][nt][0] * il, o[mt][nt][1] * il);
            *(float2*)(O + r1 * 96 + col) = make_float2(o[mt][nt][2] * ih, o[mt][nt][3] * ih);
        }
    }
}

// ---------------------------------------------------------------------------
extern "C" void kernel_launch(void* const* d_in, const int* in_sizes, int n_in,
                              void* d_out, int out_size)
{
    const float* qkv  = (const float*)d_in[0];
    const float* grid = (const float*)d_in[1];
    const float* W0  = (const float*)d_in[2];
    const float* B0  = (const float*)d_in[3];
    const float* G1  = (const float*)d_in[4];
    const float* Be1 = (const float*)d_in[5];
    const float* W1  = (const float*)d_in[6];
    const float* B1  = (const float*)d_in[7];
    const float* G2  = (const float*)d_in[8];
    const float* Be2 = (const float*)d_in[9];
    const float* W2  = (const float*)d_in[10];
    const float* B2  = (const float*)d_in[11];
    const float* G3  = (const float*)d_in[12];
    const float* Be3 = (const float*)d_in[13];
    const float* W3  = (const float*)d_in[14];
    const float* B3  = (const float*)d_in[15];
    float* out = (float*)d_out;

    const int SMEM = SMEM_WORDS * sizeof(float);   // ~33.2 KB -> 3 CTA/SM
    cudaFuncSetAttribute(pass1_kernel, cudaFuncAttributeMaxDynamicSharedMemorySize, SMEM);
    cudaFuncSetAttribute(pass2_kernel, cudaFuncAttributeMaxDynamicSharedMemorySize, SMEM);

    pass1_kernel<<<NB * NHEAD * 2, 256, SMEM>>>(qkv, grid, POSARGS);
    pass2_kernel<<<NB * NHEAD * 2, 256, SMEM>>>(qkv, grid, POSARGS, out);
}

// round 13
// speedup vs baseline: 1.0998x; 1.0998x over previous
#include <cuda_runtime.h>
#include <cuda_fp16.h>

// Problem constants: b=48, n=512, DIM=96, HEADS=6, hd=16, h=w=d=8
#define NB 48
#define NTOK 512
#define NHEAD 6
#define NPOS 43
#define L2E 1.4426950408889634f
#define QS (0.25f * L2E)     // attention scale folded with log2(e)

// ---------------------------------------------------------------------------
// helpers
// ---------------------------------------------------------------------------
__device__ __forceinline__ unsigned pkh(float lo, float hi) {   // f16x2 {lo,hi}
    unsigned d; asm("cvt.rn.f16x2.f32 %0,%1,%2;" : "=r"(d) : "f"(hi), "f"(lo)); return d;
}
__device__ __forceinline__ unsigned hex2(unsigned x) {          // 2^x on f16x2
    unsigned r; asm("ex2.approx.f16x2 %0,%1;" : "=r"(r) : "r"(x)); return r;
}
__device__ __forceinline__ unsigned hadd2u(unsigned a, unsigned b) {
    unsigned r; asm("add.f16x2 %0,%1,%2;" : "=r"(r) : "r"(a), "r"(b)); return r;
}
__device__ __forceinline__ float2 h2f2(unsigned u) {            // f16x2 -> 2 floats
    __half2 h = *reinterpret_cast<__half2*>(&u);
    return __half22float2(h);
}
// fp16 mma, fp32 accumulate in place
__device__ __forceinline__ void mma_f16(
    float& c0, float& c1, float& c2, float& c3,
    unsigned a0, unsigned a1, unsigned a2, unsigned a3,
    unsigned b0, unsigned b1)
{
    asm("mma.sync.aligned.m16n8k16.row.col.f32.f16.f16.f32 "
        "{%0,%1,%2,%3},{%4,%5,%6,%7},{%8,%9},{%0,%1,%2,%3};"
        : "+f"(c0), "+f"(c1), "+f"(c2), "+f"(c3)
        : "r"(a0), "r"(a1), "r"(a2), "r"(a3), "r"(b0), "r"(b1));
}
// fp16 mma, fp16 accumulator (C-in = packed bias, D = packed S+bias)
__device__ __forceinline__ void mma_f16h(
    unsigned& d0, unsigned& d1,
    unsigned a0, unsigned a1, unsigned a2, unsigned a3,
    unsigned b0, unsigned b1, unsigned c0, unsigned c1)
{
    asm("mma.sync.aligned.m16n8k16.row.col.f16.f16.f16.f16 "
        "{%0,%1},{%2,%3,%4,%5},{%6,%7},{%8,%9};"
        : "=r"(d0), "=r"(d1)
        : "r"(a0), "r"(a1), "r"(a2), "r"(a3), "r"(b0), "r"(b1),
          "r"(c0), "r"(c1));
}
__device__ __forceinline__ int ds9(int t) {   // base-8 digit sum, t < 512
    return (t >> 6) + ((t >> 3) & 7) + (t & 7);
}

// smem word offsets (4B words)
#define SK1 0
#define SV1 4096
#define SK2 8192
#define SV2 12288
#define SP1 16384            // fp32 pos table 1 (43)
#define SP2 16432            // fp32 pos table 2 (43)
#define SB1 16480            // packed f16x2 bias-pair table 1 (48)
#define SB2 16528            // packed f16x2 bias-pair table 2 (48)
#define SMEM_WORDS 16576

// ---------------------------------------------------------------------------
// attention core: 32 blocks of 16 keys.
// S-mma: fp16 accumulator initialized with packed bias pairs -> D is directly
// the PV A-frag after ex2.f16x2. Row sums: per-lane fp32 partials via
// HADD2 + packed h2->f32 (fma/alu pipes), quad-reduced in the epilogue.
// ---------------------------------------------------------------------------
__device__ __forceinline__ void attn_core(
    const float* __restrict__ Qp, int qt,
    const unsigned* __restrict__ sK, const unsigned* __restrict__ sV,
    const unsigned* __restrict__ sB,   // packed pairs (sPos[i], sPos[i-1])
    int warp, int lane,
    float o[4][2][4], float sL[4], float sH[4])
{
    int lq = lane >> 2, lr = lane & 3;

    unsigned qa[4][4];
    int ib[4];
#pragma unroll
    for (int mt = 0; mt < 4; ++mt) {
        int r0 = warp * 64 + mt * 16 + lq;
        float2 qv0 = *(const float2*)(Qp + r0 * qt + 2 * lr);
        float2 qv1 = *(const float2*)(Qp + r0 * qt + 8 + 2 * lr);
        float2 qv2 = *(const float2*)(Qp + (r0 + 8) * qt + 2 * lr);
        float2 qv3 = *(const float2*)(Qp + (r0 + 8) * qt + 8 + 2 * lr);
        qa[mt][0] = pkh(qv0.x * QS, qv0.y * QS);   // row lq,   k 2lr..
        qa[mt][1] = pkh(qv2.x * QS, qv2.y * QS);   // row lq+8, k 2lr..
        qa[mt][2] = pkh(qv1.x * QS, qv1.y * QS);   // row lq,   k 8+2lr..
        qa[mt][3] = pkh(qv3.x * QS, qv3.y * QS);   // row lq+8, k 8+2lr..
        ib[mt] = ds9(r0) + 21 - 2 * lr;
#pragma unroll
        for (int nt = 0; nt < 2; ++nt)
#pragma unroll
            for (int j = 0; j < 4; ++j) o[mt][nt][j] = 0.f;
        sL[mt] = 0.f; sH[mt] = 0.f;
    }

    for (int blk = 0; blk < 32; ++blk) {
        uint2 k0 = *(const uint2*)(sK + (blk * 2 + 0) * 64 + lane * 2);
        uint2 k1 = *(const uint2*)(sK + (blk * 2 + 1) * 64 + lane * 2);
        uint2 v0 = *(const uint2*)(sV + (blk * 2 + 0) * 64 + lane * 2);
        uint2 v1 = *(const uint2*)(sV + (blk * 2 + 1) * 64 + lane * 2);
        int dsb = (blk >> 2) + ((2 * blk) & 7);

#pragma unroll
        for (int mt = 0; mt < 4; ++mt) {
            int i0 = ib[mt] - dsb;
            unsigned b0 = sB[i0];
            unsigned bp = sB[i0 + 1];
            unsigned bm = sB[i0 - 1];

            unsigned e0, e1, f0, f1;
            // ntile0: C-init {P2[i0], P2[i0+1]}  (rows lq / lq+8)
            mma_f16h(e0, e1, qa[mt][0], qa[mt][1], qa[mt][2], qa[mt][3],
                     k0.x, k0.y, b0, bp);
            // ntile1: cols+8 -> ds+1 -> C-init {P2[i0-1], P2[i0]}
            mma_f16h(f0, f1, qa[mt][0], qa[mt][1], qa[mt][2], qa[mt][3],
                     k1.x, k1.y, bm, b0);

            unsigned a0 = hex2(e0);   // row lq,   keys 2lr,2lr+1
            unsigned a1 = hex2(e1);   // row lq+8, keys 2lr,2lr+1
            unsigned a2 = hex2(f0);   // row lq,   keys 8+2lr..
            unsigned a3 = hex2(f1);   // row lq+8, keys 8+2lr..

            // per-lane fp32 sum partials (each lane owns 4 keys per row-half)
            float2 slo = h2f2(hadd2u(a0, a2));
            float2 shi = h2f2(hadd2u(a1, a3));
            sL[mt] += slo.x + slo.y;
            sH[mt] += shi.x + shi.y;

            mma_f16(o[mt][0][0], o[mt][0][1], o[mt][0][2], o[mt][0][3],
                    a0, a1, a2, a3, v0.x, v0.y);
            mma_f16(o[mt][1][0], o[mt][1][1], o[mt][1][2], o[mt][1][3],
                    a0, a1, a2, a3, v1.x, v1.y);
        }
    }
}

// ---------------------------------------------------------------------------
// Fully fused kernel: one CTA per (b,head).
// ---------------------------------------------------------------------------
__global__ __launch_bounds__(256, 2) void fused_kernel(
    const float* __restrict__ qkv, const float* __restrict__ grid,
    const float* __restrict__ W0, const float* __restrict__ B0,
    const float* __restrict__ G1, const float* __restrict__ Be1,
    const float* __restrict__ W1, const float* __restrict__ B1,
    const float* __restrict__ G2, const float* __restrict__ Be2,
    const float* __restrict__ W2, const float* __restrict__ B2,
    const float* __restrict__ G3, const float* __restrict__ Be3,
    const float* __restrict__ W3, const float* __restrict__ B3,
    float* __restrict__ out)
{
    extern __shared__ float sm[];
    unsigned* sK1 = (unsigned*)(sm + SK1);
    unsigned* sV1 = (unsigned*)(sm + SV1);
    unsigned* sK2 = (unsigned*)(sm + SK2);
    unsigned* sV2 = (unsigned*)(sm + SV2);
    float* sPos1 = sm + SP1;
    float* sPos2 = sm + SP2;
    unsigned* sB1 = (unsigned*)(sm + SB1);
    unsigned* sB2 = (unsigned*)(sm + SB2);

    int bh = blockIdx.x;
    int b = bh / NHEAD, h = bh % NHEAD;
    const float* qkvB = qkv + (long)b * NTOK * 288;
    const float* gridB = grid + (long)b * NTOK * 96;

    int tid = threadIdx.x;

    // ---- stage K1 (qkv.k), K2 (grid) as fp16 K-B-frags; V1 (qkv.v) as fp16 V-B-frags
    for (int e = tid; e < NTOK * 4; e += 256) {
        int key = e >> 2;
        int c4 = (e & 3) * 4;
        float4 kv = *(const float4*)(qkvB + key * 288 + 96 + h * 16 + c4);
        float4 vv = *(const float4*)(qkvB + key * 288 + 192 + h * 16 + c4);
        float4 gv = *(const float4*)(gridB + key * 96 + h * 16 + c4);
        float kj[4] = { kv.x, kv.y, kv.z, kv.w };
        float vj[4] = { vv.x, vv.y, vv.z, vv.w };
        float gj[4] = { gv.x, gv.y, gv.z, gv.w };
        int blk = key >> 4, kl = key & 15;
        int ntK = kl >> 3, lqK = kl & 7;
        // K/G: two f16x2 words (dims c4..c4+1, c4+2..c4+3)
#pragma unroll
        for (int jp = 0; jp < 2; ++jp) {
            int d = c4 + 2 * jp;
            int w = (blk * 2 + ntK) * 64 + lqK * 8 + ((d & 7) >> 1) * 2 + (d >> 3);
            sK1[w] = pkh(kj[2 * jp], kj[2 * jp + 1]);
            sK2[w] = pkh(gj[2 * jp], gj[2 * jp + 1]);
        }
        // V: 4 half stores
        int lrV = (kl & 7) >> 1, regV = kl >> 3, hfV = kl & 1;
#pragma unroll
        for (int j = 0; j < 4; ++j) {
            int dim = c4 + j;
            int w = (blk * 2 + (dim >> 3)) * 64 + (dim & 7) * 8 + lrV * 2 + regV;
            ((__half*)sV1)[w * 2 + hfV] = __float2half_rn(vj[j]);
        }
    }

    // ---- inline pos-MLP: threads 0..85 compute the two 43-row tables ----
    if (tid < 86) {
        int i = (tid >= NPOS) ? 1 : 0;
        int m = tid - i * NPOS;
        float bh_ = -7.f;
        float bw_ = (float)(m / 15) - 7.f;
        float bd_ = (float)(m % 15) - 7.f;
        float x[6], y[6];
#pragma unroll
        for (int j = 0; j < 6; ++j) {
            const float* w = W0 + (i * 6 + j) * 3;
            x[j] = bh_ * w[0] + bw_ * w[1] + bd_ * w[2] + B0[i * 6 + j];
        }
        {
            float mu = 0.f;
#pragma unroll
            for (int j = 0; j < 6; ++j) mu += x[j];
            mu *= (1.f / 6.f);
            float var = 0.f;
#pragma unroll
            for (int j = 0; j < 6; ++j) { float d = x[j] - mu; var += d * d; }
            float inv = rsqrtf(var * (1.f / 6.f) + 1e-5f);
#pragma unroll
            for (int j = 0; j < 6; ++j)
                x[j] = fmaxf((x[j] - mu) * inv * G1[i * 6 + j] + Be1[i * 6 + j], 0.f);
#pragma unroll
            for (int j = 0; j < 6; ++j) {
                const float* w = W1 + (i * 6 + j) * 6;
                float s = B1[i * 6 + j];
#pragma unroll
                for (int k = 0; k < 6; ++k) s += x[k] * w[k];
                y[j] = s;
            }
        }
        {
            float mu = 0.f;
#pragma unroll
            for (int j = 0; j < 6; ++j) mu += y[j];
            mu *= (1.f / 6.f);
            float var = 0.f;
#pragma unroll
            for (int j = 0; j < 6; ++j) { float d = y[j] - mu; var += d * d; }
            float inv = rsqrtf(var * (1.f / 6.f) + 1e-5f);
#pragma unroll
            for (int j = 0; j < 6; ++j)
                y[j] = fmaxf((y[j] - mu) * inv * G2[i * 6 + j] + Be2[i * 6 + j], 0.f);
#pragma unroll
            for (int j = 0; j < 6; ++j) {
                const float* w = W2 + (i * 6 + j) * 6;
                float s = B2[i * 6 + j];
#pragma unroll
                for (int k = 0; k < 6; ++k) s += y[k] * w[k];
                x[j] = s;
            }
        }
        {
            float mu = 0.f;
#pragma unroll
            for (int j = 0; j < 6; ++j) mu += x[j];
            mu *= (1.f / 6.f);
            float var = 0.f;
#pragma unroll
            for (int j = 0; j < 6; ++j) { float d = x[j] - mu; var += d * d; }
            float inv = rsqrtf(var * (1.f / 6.f) + 1e-5f);
#pragma unroll
            for (int j = 0; j < 6; ++j)
                x[j] = fmaxf((x[j] - mu) * inv * G3[i * 6 + j] + Be3[i * 6 + j], 0.f);
            const float* w = W3 + (i * NHEAD + h) * 6;
            float s = B3[i * NHEAD + h];
#pragma unroll
            for (int k = 0; k < 6; ++k) s += x[k] * w[k];
            ((i == 0) ? sPos1 : sPos2)[m] = s * L2E;
        }
    }
    __syncthreads();

    // ---- build packed bias-pair tables: sB[i] = (sPos[i], sPos[i-1]) as f16x2
    if (tid < 96) {
        int i = (tid >= 48) ? 1 : 0;
        int m = tid - i * 48;
        const float* sp = i ? sPos2 : sPos1;
        float lo = (m < NPOS) ? sp[m] : 0.f;
        float hi = (m >= 1 && m - 1 < NPOS) ? sp[m - 1] : 0.f;
        ((i == 0) ? sB1 : sB2)[m] = pkh(lo, hi);
    }
    __syncthreads();

    int warp = tid >> 5, lane = tid & 31, lq = lane >> 2, lr = lane & 3;
    float o[4][2][4], sL[4], sH[4];

    // ================= PASS 1: Q=grid, K=qkv.k, V=qkv.v =================
    attn_core(gridB + h * 16, 96, sK1, sV1, sB1, warp, lane, o, sL, sH);

    // normalize; write x1 into sV2 (fp16 V-B-frag layout; rows become keys)
#pragma unroll
    for (int mt = 0; mt < 4; ++mt) {
        float sl = sL[mt], sh = sH[mt];
        sl += __shfl_xor_sync(0xffffffffu, sl, 1);
        sl += __shfl_xor_sync(0xffffffffu, sl, 2);
        sh += __shfl_xor_sync(0xffffffffu, sh, 1);
        sh += __shfl_xor_sync(0xffffffffu, sh, 2);
        float il = 1.f / sl, ih = 1.f / sh;
        int r0 = warp * 64 + mt * 16 + lq;
#pragma unroll
        for (int nt = 0; nt < 2; ++nt) {
#pragma unroll
            for (int j = 0; j < 4; ++j) {
                float val = o[mt][nt][j] * ((j < 2) ? il : ih);
                int row = (j < 2) ? r0 : (r0 + 8);
                int col = nt * 8 + 2 * lr + (j & 1);
                int kb = row & 15;
                int w = ((row >> 4) * 2 + nt) * 64 + (col & 7) * 8 + ((kb & 7) >> 1) * 2 + (kb >> 3);
                ((__half*)sV2)[w * 2 + (kb & 1)] = __float2half_rn(val);
            }
        }
    }
    __syncthreads();

    // ================= PASS 2: Q=qkv.q, K=grid, V=x1 =================
    attn_core(qkvB + h * 16, 288, sK2, sV2, sB2, warp, lane, o, sL, sH);

    float* O = out + (long)b * NTOK * 96 + h * 16;
#pragma unroll
    for (int mt = 0; mt < 4; ++mt) {
        float sl = sL[mt], sh = sH[mt];
        sl += __shfl_xor_sync(0xffffffffu, sl, 1);
        sl += __shfl_xor_sync(0xffffffffu, sl, 2);
        sh += __shfl_xor_sync(0xffffffffu, sh, 1);
        sh += __shfl_xor_sync(0xffffffffu, sh, 2);
        float il = 1.f / sl, ih = 1.f / sh;
        int r0 = warp * 64 + mt * 16 + lq, r1 = r0 + 8;
#pragma unroll
        for (int nt = 0; nt < 2; ++nt) {
            int col = nt * 8 + 2 * lr;
            *(float2*)(O + r0 * 96 + col) = make_float2(o[mt][nt][0] * il, o[mt][nt][1] * il);
            *(float2*)(O + r1 * 96 + col) = make_float2(o[mt][nt][2] * ih, o[mt][nt][3] * ih);
        }
    }
}

// ---------------------------------------------------------------------------
extern "C" void kernel_launch(void* const* d_in, const int* in_sizes, int n_in,
                              void* d_out, int out_size)
{
    const float* qkv  = (const float*)d_in[0];
    const float* grid = (const float*)d_in[1];
    const float* W0  = (const float*)d_in[2];
    const float* B0  = (const float*)d_in[3];
    const float* G1  = (const float*)d_in[4];
    const float* Be1 = (const float*)d_in[5];
    const float* W1  = (const float*)d_in[6];
    const float* B1  = (const float*)d_in[7];
    const float* G2  = (const float*)d_in[8];
    const float* Be2 = (const float*)d_in[9];
    const float* W2  = (const float*)d_in[10];
    const float* B2  = (const float*)d_in[11];
    const float* G3  = (const float*)d_in[12];
    const float* Be3 = (const float*)d_in[13];
    const float* W3  = (const float*)d_in[14];
    const float* B3  = (const float*)d_in[15];
    float* out = (float*)d_out;

    const int SMEM = SMEM_WORDS * sizeof(float);   // ~66.3 KB -> 2 CTA/SM
    cudaFuncSetAttribute(fused_kernel, cudaFuncAttributeMaxDynamicSharedMemorySize, SMEM);

    fused_kernel<<<NB * NHEAD, 256, SMEM>>>(
        qkv, grid, W0, B0, G1, Be1, W1, B1, G2, Be2, W2, B2, G3, Be3, W3, B3, out);
}

// round 14
// speedup vs baseline: 1.1884x; 1.0805x over previous
#include <cuda_runtime.h>
#include <cuda_fp16.h>

// Problem constants: b=48, n=512, DIM=96, HEADS=6, hd=16, h=w=d=8
#define NB 48
#define NTOK 512
#define NHEAD 6
#define NPOS 43
#define L2E 1.4426950408889634f
#define QS (0.25f * L2E)     // attention scale folded with log2(e)

// ---------------------------------------------------------------------------
// helpers
// ---------------------------------------------------------------------------
__device__ __forceinline__ unsigned pkh(float lo, float hi) {   // f16x2 {lo,hi}
    unsigned d; asm("cvt.rn.f16x2.f32 %0,%1,%2;" : "=r"(d) : "f"(hi), "f"(lo)); return d;
}
__device__ __forceinline__ unsigned hex2(unsigned x) {          // 2^x on f16x2
    unsigned r; asm("ex2.approx.f16x2 %0,%1;" : "=r"(r) : "r"(x)); return r;
}
// fp16 mma, fp32 accumulate in place
__device__ __forceinline__ void mma_f16(
    float& c0, float& c1, float& c2, float& c3,
    unsigned a0, unsigned a1, unsigned a2, unsigned a3,
    unsigned b0, unsigned b1)
{
    asm("mma.sync.aligned.m16n8k16.row.col.f32.f16.f16.f32 "
        "{%0,%1,%2,%3},{%4,%5,%6,%7},{%8,%9},{%0,%1,%2,%3};"
        : "+f"(c0), "+f"(c1), "+f"(c2), "+f"(c3)
        : "r"(a0), "r"(a1), "r"(a2), "r"(a3), "r"(b0), "r"(b1));
}
// fp16 mma, fp16 accumulator (C-in = packed bias, D = packed S+bias)
__device__ __forceinline__ void mma_f16h(
    unsigned& d0, unsigned& d1,
    unsigned a0, unsigned a1, unsigned a2, unsigned a3,
    unsigned b0, unsigned b1, unsigned c0, unsigned c1)
{
    asm("mma.sync.aligned.m16n8k16.row.col.f16.f16.f16.f16 "
        "{%0,%1},{%2,%3,%4,%5},{%6,%7},{%8,%9};"
        : "=r"(d0), "=r"(d1)
        : "r"(a0), "r"(a1), "r"(a2), "r"(a3), "r"(b0), "r"(b1),
          "r"(c0), "r"(c1));
}
__device__ __forceinline__ int ds9(int t) {   // base-8 digit sum, t < 512
    return (t >> 6) + ((t >> 3) & 7) + (t & 7);
}

// smem word offsets (4B words)
#define SK1 0
#define SV1 4096
#define SK2 8192
#define SV2 12288
#define SP1 16384            // fp32 pos table 1 (43)
#define SP2 16432            // fp32 pos table 2 (43)
#define SB1 16480            // packed f16x2 bias-pair table 1 (48)
#define SB2 16528            // packed f16x2 bias-pair table 2 (48)
#define SQ1 16576            // uint4 bias-quad table 1 (48 x 4 words, 16B aligned)
#define SQ2 16768            // uint4 bias-quad table 2 (48 x 4 words)
#define SMEM_WORDS 16960

// ---------------------------------------------------------------------------
// attention core: 32 blocks of 16 keys.
// S-mma: fp16 accumulator initialized with packed bias pairs (single LDS.128
// per m-tile per block: sQ[i] = {B[i], B[i+1], B[i-1], -}). P = ex2.f16x2 of
// the mma output feeds PV mmas directly. Row sums via a ones-column mma.
// ---------------------------------------------------------------------------
__device__ __forceinline__ void attn_core(
    const float* __restrict__ Qp, int qt,
    const unsigned* __restrict__ sK, const unsigned* __restrict__ sV,
    const uint4* __restrict__ sQ,
    int warp, int lane,
    float o[4][2][4], float oS[4][4])
{
    int lq = lane >> 2, lr = lane & 3;
    unsigned bsum = (lq == 0) ? 0x3C003C00u : 0u;   // ones column B-frag

    unsigned qa[4][4];
    int ib[4];
#pragma unroll
    for (int mt = 0; mt < 4; ++mt) {
        int r0 = warp * 64 + mt * 16 + lq;
        float2 qv0 = *(const float2*)(Qp + r0 * qt + 2 * lr);
        float2 qv1 = *(const float2*)(Qp + r0 * qt + 8 + 2 * lr);
        float2 qv2 = *(const float2*)(Qp + (r0 + 8) * qt + 2 * lr);
        float2 qv3 = *(const float2*)(Qp + (r0 + 8) * qt + 8 + 2 * lr);
        qa[mt][0] = pkh(qv0.x * QS, qv0.y * QS);   // row lq,   k 2lr..
        qa[mt][1] = pkh(qv2.x * QS, qv2.y * QS);   // row lq+8, k 2lr..
        qa[mt][2] = pkh(qv1.x * QS, qv1.y * QS);   // row lq,   k 8+2lr..
        qa[mt][3] = pkh(qv3.x * QS, qv3.y * QS);   // row lq+8, k 8+2lr..
        ib[mt] = ds9(r0) + 21 - 2 * lr;
#pragma unroll
        for (int nt = 0; nt < 2; ++nt)
#pragma unroll
            for (int j = 0; j < 4; ++j) o[mt][nt][j] = 0.f;
#pragma unroll
        for (int j = 0; j < 4; ++j) oS[mt][j] = 0.f;
    }

#pragma unroll 4
    for (int blk = 0; blk < 32; ++blk) {
        uint2 k0 = *(const uint2*)(sK + (blk * 2 + 0) * 64 + lane * 2);
        uint2 k1 = *(const uint2*)(sK + (blk * 2 + 1) * 64 + lane * 2);
        uint2 v0 = *(const uint2*)(sV + (blk * 2 + 0) * 64 + lane * 2);
        uint2 v1 = *(const uint2*)(sV + (blk * 2 + 1) * 64 + lane * 2);
        int dsb = (blk >> 2) + ((2 * blk) & 7);

#pragma unroll
        for (int mt = 0; mt < 4; ++mt) {
            int i0 = ib[mt] - dsb;
            uint4 bq = sQ[i0];     // .x = B[i0], .y = B[i0+1], .z = B[i0-1]

            unsigned e0, e1, f0, f1;
            // ntile0: C-init {B[i0], B[i0+1]}  (rows lq / lq+8)
            mma_f16h(e0, e1, qa[mt][0], qa[mt][1], qa[mt][2], qa[mt][3],
                     k0.x, k0.y, bq.x, bq.y);
            // ntile1: cols+8 -> ds+1 -> C-init {B[i0-1], B[i0]}
            mma_f16h(f0, f1, qa[mt][0], qa[mt][1], qa[mt][2], qa[mt][3],
                     k1.x, k1.y, bq.z, bq.x);

            unsigned a0 = hex2(e0);   // row lq,   keys 2lr,2lr+1
            unsigned a1 = hex2(e1);   // row lq+8, keys 2lr,2lr+1
            unsigned a2 = hex2(f0);   // row lq,   keys 8+2lr..
            unsigned a3 = hex2(f1);   // row lq+8, keys 8+2lr..

            mma_f16(o[mt][0][0], o[mt][0][1], o[mt][0][2], o[mt][0][3],
                    a0, a1, a2, a3, v0.x, v0.y);
            mma_f16(o[mt][1][0], o[mt][1][1], o[mt][1][2], o[mt][1][3],
                    a0, a1, a2, a3, v1.x, v1.y);
            mma_f16(oS[mt][0], oS[mt][1], oS[mt][2], oS[mt][3],
                    a0, a1, a2, a3, bsum, bsum);
        }
    }
}

// ---------------------------------------------------------------------------
// Fully fused kernel: one CTA per (b,head).
// ---------------------------------------------------------------------------
__global__ __launch_bounds__(256, 2) void fused_kernel(
    const float* __restrict__ qkv, const float* __restrict__ grid,
    const float* __restrict__ W0, const float* __restrict__ B0,
    const float* __restrict__ G1, const float* __restrict__ Be1,
    const float* __restrict__ W1, const float* __restrict__ B1,
    const float* __restrict__ G2, const float* __restrict__ Be2,
    const float* __restrict__ W2, const float* __restrict__ B2,
    const float* __restrict__ G3, const float* __restrict__ Be3,
    const float* __restrict__ W3, const float* __restrict__ B3,
    float* __restrict__ out)
{
    extern __shared__ float sm[];
    unsigned* sK1 = (unsigned*)(sm + SK1);
    unsigned* sV1 = (unsigned*)(sm + SV1);
    unsigned* sK2 = (unsigned*)(sm + SK2);
    unsigned* sV2 = (unsigned*)(sm + SV2);
    float* sPos1 = sm + SP1;
    float* sPos2 = sm + SP2;
    unsigned* sB1 = (unsigned*)(sm + SB1);
    unsigned* sB2 = (unsigned*)(sm + SB2);
    uint4* sQ1 = (uint4*)(sm + SQ1);
    uint4* sQ2 = (uint4*)(sm + SQ2);

    int bh = blockIdx.x;
    int b = bh / NHEAD, h = bh % NHEAD;
    const float* qkvB = qkv + (long)b * NTOK * 288;
    const float* gridB = grid + (long)b * NTOK * 96;

    int tid = threadIdx.x;

    // ---- stage K1 (qkv.k), K2 (grid) as fp16 K-B-frags; V1 (qkv.v) as fp16 V-B-frags
    for (int e = tid; e < NTOK * 4; e += 256) {
        int key = e >> 2;
        int c4 = (e & 3) * 4;
        float4 kv = *(const float4*)(qkvB + key * 288 + 96 + h * 16 + c4);
        float4 vv = *(const float4*)(qkvB + key * 288 + 192 + h * 16 + c4);
        float4 gv = *(const float4*)(gridB + key * 96 + h * 16 + c4);
        float kj[4] = { kv.x, kv.y, kv.z, kv.w };
        float vj[4] = { vv.x, vv.y, vv.z, vv.w };
        float gj[4] = { gv.x, gv.y, gv.z, gv.w };
        int blk = key >> 4, kl = key & 15;
        int ntK = kl >> 3, lqK = kl & 7;
        // K/G: two f16x2 words (dims c4..c4+1, c4+2..c4+3)
#pragma unroll
        for (int jp = 0; jp < 2; ++jp) {
            int d = c4 + 2 * jp;
            int w = (blk * 2 + ntK) * 64 + lqK * 8 + ((d & 7) >> 1) * 2 + (d >> 3);
            sK1[w] = pkh(kj[2 * jp], kj[2 * jp + 1]);
            sK2[w] = pkh(gj[2 * jp], gj[2 * jp + 1]);
        }
        // V: 4 half stores
        int lrV = (kl & 7) >> 1, regV = kl >> 3, hfV = kl & 1;
#pragma unroll
        for (int j = 0; j < 4; ++j) {
            int dim = c4 + j;
            int w = (blk * 2 + (dim >> 3)) * 64 + (dim & 7) * 8 + lrV * 2 + regV;
            ((__half*)sV1)[w * 2 + hfV] = __float2half_rn(vj[j]);
        }
    }

    // ---- inline pos-MLP: threads 0..85 compute the two 43-row tables ----
    if (tid < 86) {
        int i = (tid >= NPOS) ? 1 : 0;
        int m = tid - i * NPOS;
        float bh_ = -7.f;
        float bw_ = (float)(m / 15) - 7.f;
        float bd_ = (float)(m % 15) - 7.f;
        float x[6], y[6];
#pragma unroll
        for (int j = 0; j < 6; ++j) {
            const float* w = W0 + (i * 6 + j) * 3;
            x[j] = bh_ * w[0] + bw_ * w[1] + bd_ * w[2] + B0[i * 6 + j];
        }
        {
            float mu = 0.f;
#pragma unroll
            for (int j = 0; j < 6; ++j) mu += x[j];
            mu *= (1.f / 6.f);
            float var = 0.f;
#pragma unroll
            for (int j = 0; j < 6; ++j) { float d = x[j] - mu; var += d * d; }
            float inv = rsqrtf(var * (1.f / 6.f) + 1e-5f);
#pragma unroll
            for (int j = 0; j < 6; ++j)
                x[j] = fmaxf((x[j] - mu) * inv * G1[i * 6 + j] + Be1[i * 6 + j], 0.f);
#pragma unroll
            for (int j = 0; j < 6; ++j) {
                const float* w = W1 + (i * 6 + j) * 6;
                float s = B1[i * 6 + j];
#pragma unroll
                for (int k = 0; k < 6; ++k) s += x[k] * w[k];
                y[j] = s;
            }
        }
        {
            float mu = 0.f;
#pragma unroll
            for (int j = 0; j < 6; ++j) mu += y[j];
            mu *= (1.f / 6.f);
            float var = 0.f;
#pragma unroll
            for (int j = 0; j < 6; ++j) { float d = y[j] - mu; var += d * d; }
            float inv = rsqrtf(var * (1.f / 6.f) + 1e-5f);
#pragma unroll
            for (int j = 0; j < 6; ++j)
                y[j] = fmaxf((y[j] - mu) * inv * G2[i * 6 + j] + Be2[i * 6 + j], 0.f);
#pragma unroll
            for (int j = 0; j < 6; ++j) {
                const float* w = W2 + (i * 6 + j) * 6;
                float s = B2[i * 6 + j];
#pragma unroll
                for (int k = 0; k < 6; ++k) s += y[k] * w[k];
                x[j] = s;
            }
        }
        {
            float mu = 0.f;
#pragma unroll
            for (int j = 0; j < 6; ++j) mu += x[j];
            mu *= (1.f / 6.f);
            float var = 0.f;
#pragma unroll
            for (int j = 0; j < 6; ++j) { float d = x[j] - mu; var += d * d; }
            float inv = rsqrtf(var * (1.f / 6.f) + 1e-5f);
#pragma unroll
            for (int j = 0; j < 6; ++j)
                x[j] = fmaxf((x[j] - mu) * inv * G3[i * 6 + j] + Be3[i * 6 + j], 0.f);
            const float* w = W3 + (i * NHEAD + h) * 6;
            float s = B3[i * NHEAD + h];
#pragma unroll
            for (int k = 0; k < 6; ++k) s += x[k] * w[k];
            ((i == 0) ? sPos1 : sPos2)[m] = s * L2E;
        }
    }
    __syncthreads();

    // ---- build packed bias-pair tables: sB[i] = (sPos[i], sPos[i-1]) as f16x2
    if (tid < 96) {
        int i = (tid >= 48) ? 1 : 0;
        int m = tid - i * 48;
        const float* sp = i ? sPos2 : sPos1;
        float lo = (m < NPOS) ? sp[m] : 0.f;
        float hi = (m >= 1 && m - 1 < NPOS) ? sp[m - 1] : 0.f;
        ((i == 0) ? sB1 : sB2)[m] = pkh(lo, hi);
    }
    __syncthreads();

    // ---- build bias-quad tables: sQ[i] = {sB[i], sB[i+1], sB[i-1], 0}
    if (tid < 96) {
        int i = (tid >= 48) ? 1 : 0;
        int m = tid - i * 48;
        const unsigned* sb = i ? sB2 : sB1;
        uint4 q;
        q.x = sb[m];
        q.y = (m < 47) ? sb[m + 1] : 0u;
        q.z = (m >= 1) ? sb[m - 1] : 0u;
        q.w = 0u;
        ((i == 0) ? sQ1 : sQ2)[m] = q;
    }
    __syncthreads();

    int warp = tid >> 5, lane = tid & 31, lq = lane >> 2, lr = lane & 3;
    float o[4][2][4], oS[4][4];

    // ================= PASS 1: Q=grid, K=qkv.k, V=qkv.v =================
    attn_core(gridB + h * 16, 96, sK1, sV1, sQ1, warp, lane, o, oS);

    // normalize; write x1 into sV2 (fp16 V-B-frag layout; rows become keys)
#pragma unroll
    for (int mt = 0; mt < 4; ++mt) {
        float sl = __shfl_sync(0xffffffffu, oS[mt][0], lane & ~3);
        float sh = __shfl_sync(0xffffffffu, oS[mt][2], lane & ~3);
        float il = 1.f / sl, ih = 1.f / sh;
        int r0 = warp * 64 + mt * 16 + lq;
#pragma unroll
        for (int nt = 0; nt < 2; ++nt) {
#pragma unroll
            for (int j = 0; j < 4; ++j) {
                float val = o[mt][nt][j] * ((j < 2) ? il : ih);
                int row = (j < 2) ? r0 : (r0 + 8);
                int col = nt * 8 + 2 * lr + (j & 1);
                int kb = row & 15;
                int w = ((row >> 4) * 2 + nt) * 64 + (col & 7) * 8 + ((kb & 7) >> 1) * 2 + (kb >> 3);
                ((__half*)sV2)[w * 2 + (kb & 1)] = __float2half_rn(val);
            }
        }
    }
    __syncthreads();

    // ================= PASS 2: Q=qkv.q, K=grid, V=x1 =================
    attn_core(qkvB + h * 16, 288, sK2, sV2, sQ2, warp, lane, o, oS);

    float* O = out + (long)b * NTOK * 96 + h * 16;
#pragma unroll
    for (int mt = 0; mt < 4; ++mt) {
        float sl = __shfl_sync(0xffffffffu, oS[mt][0], lane & ~3);
        float sh = __shfl_sync(0xffffffffu, oS[mt][2], lane & ~3);
        float il = 1.f / sl, ih = 1.f / sh;
        int r0 = warp * 64 + mt * 16 + lq, r1 = r0 + 8;
#pragma unroll
        for (int nt = 0; nt < 2; ++nt) {
            int col = nt * 8 + 2 * lr;
            *(float2*)(O + r0 * 96 + col) = make_float2(o[mt][nt][0] * il, o[mt][nt][1] * il);
            *(float2*)(O + r1 * 96 + col) = make_float2(o[mt][nt][2] * ih, o[mt][nt][3] * ih);
        }
    }
}

// ---------------------------------------------------------------------------
extern "C" void kernel_launch(void* const* d_in, const int* in_sizes, int n_in,
                              void* d_out, int out_size)
{
    const float* qkv  = (const float*)d_in[0];
    const float* grid = (const float*)d_in[1];
    const float* W0  = (const float*)d_in[2];
    const float* B0  = (const float*)d_in[3];
    const float* G1  = (const float*)d_in[4];
    const float* Be1 = (const float*)d_in[5];
    const float* W1  = (const float*)d_in[6];
    const float* B1  = (const float*)d_in[7];
    const float* G2  = (const float*)d_in[8];
    const float* Be2 = (const float*)d_in[9];
    const float* W2  = (const float*)d_in[10];
    const float* B2  = (const float*)d_in[11];
    const float* G3  = (const float*)d_in[12];
    const float* Be3 = (const float*)d_in[13];
    const float* W3  = (const float*)d_in[14];
    const float* B3  = (const float*)d_in[15];
    float* out = (float*)d_out;

    const int SMEM = SMEM_WORDS * sizeof(float);   // ~67.8 KB -> 2 CTA/SM
    cudaFuncSetAttribute(fused_kernel, cudaFuncAttributeMaxDynamicSharedMemorySize, SMEM);

    fused_kernel<<<NB * NHEAD, 256, SMEM>>>(
        qkv, grid, W0, B0, G1, Be1, W1, B1, G2, Be2, W2, B2, G3, Be3, W3, B3, out);
}

// round 15
// speedup vs baseline: 1.2177x; 1.0247x over previous
#include <cuda_runtime.h>
#include <cuda_fp16.h>

// Problem constants: b=48, n=512, DIM=96, HEADS=6, hd=16, h=w=d=8
#define NB 48
#define NTOK 512
#define NHEAD 6
#define NPOS 43
#define L2E 1.4426950408889634f
#define QS (0.25f * L2E)     // attention scale folded with log2(e)

// ---------------------------------------------------------------------------
// helpers
// ---------------------------------------------------------------------------
__device__ __forceinline__ unsigned pkh(float lo, float hi) {   // f16x2 {lo,hi}
    unsigned d; asm("cvt.rn.f16x2.f32 %0,%1,%2;" : "=r"(d) : "f"(hi), "f"(lo)); return d;
}
__device__ __forceinline__ unsigned hex2(unsigned x) {          // 2^x on f16x2
    unsigned r; asm("ex2.approx.f16x2 %0,%1;" : "=r"(r) : "r"(x)); return r;
}
// fp16 mma, fp32 accumulate in place
__device__ __forceinline__ void mma_f16(
    float& c0, float& c1, float& c2, float& c3,
    unsigned a0, unsigned a1, unsigned a2, unsigned a3,
    unsigned b0, unsigned b1)
{
    asm("mma.sync.aligned.m16n8k16.row.col.f32.f16.f16.f32 "
        "{%0,%1,%2,%3},{%4,%5,%6,%7},{%8,%9},{%0,%1,%2,%3};"
        : "+f"(c0), "+f"(c1), "+f"(c2), "+f"(c3)
        : "r"(a0), "r"(a1), "r"(a2), "r"(a3), "r"(b0), "r"(b1));
}
// fp16 mma, fp16 accumulator (C-in = packed bias, D = packed S+bias)
__device__ __forceinline__ void mma_f16h(
    unsigned& d0, unsigned& d1,
    unsigned a0, unsigned a1, unsigned a2, unsigned a3,
    unsigned b0, unsigned b1, unsigned c0, unsigned c1)
{
    asm("mma.sync.aligned.m16n8k16.row.col.f16.f16.f16.f16 "
        "{%0,%1},{%2,%3,%4,%5},{%6,%7},{%8,%9};"
        : "=r"(d0), "=r"(d1)
        : "r"(a0), "r"(a1), "r"(a2), "r"(a3), "r"(b0), "r"(b1),
          "r"(c0), "r"(c1));
}
__device__ __forceinline__ int ds9(int t) {   // base-8 digit sum, t < 512
    return (t >> 6) + ((t >> 3) & 7) + (t & 7);
}

// smem word offsets (4B words)
#define SK1 0
#define SV1 4096
#define SK2 8192
#define SV2 12288
#define SP1 16384            // fp32 pos table 1 (43)
#define SP2 16432            // fp32 pos table 2 (43)
#define SB1 16480            // packed f16x2 bias-pair table 1 (48)
#define SB2 16528            // packed f16x2 bias-pair table 2 (48)
#define SQ1 16576            // uint4 bias-quad table 1 (48 x 4 words)
#define SQ2 16768            // uint4 bias-quad table 2 (48 x 4 words)
#define SMEM_WORDS 16960

// ---------------------------------------------------------------------------
// attention core: 32 blocks of 16 keys, iterated as r(0..3) x qq(0..7) with
// blk = 4*qq + r  =>  dsb = qq + 2r  =>  bias index i0 decreases by 1 per qq.
// The 3-value bias window {B[i0],B[i0+1],B[i0-1]} slides by register
// rotation; only ONE new LDS.32 per mt per block. K/V addresses become
// immediate offsets off a per-segment base.
// ---------------------------------------------------------------------------
__device__ __forceinline__ void attn_core(
    const float* __restrict__ Qp, int qt,
    const unsigned* __restrict__ sK, const unsigned* __restrict__ sV,
    const uint4* __restrict__ sQ, const unsigned* __restrict__ sB,
    int warp, int lane,
    float o[4][2][4], float oS[4][4])
{
    int lq = lane >> 2, lr = lane & 3;
    unsigned bsum = (lq == 0) ? 0x3C003C00u : 0u;   // ones column B-frag

    unsigned qa[4][4];
    int ib[4];
#pragma unroll
    for (int mt = 0; mt < 4; ++mt) {
        int r0 = warp * 64 + mt * 16 + lq;
        float2 qv0 = *(const float2*)(Qp + r0 * qt + 2 * lr);
        float2 qv1 = *(const float2*)(Qp + r0 * qt + 8 + 2 * lr);
        float2 qv2 = *(const float2*)(Qp + (r0 + 8) * qt + 2 * lr);
        float2 qv3 = *(const float2*)(Qp + (r0 + 8) * qt + 8 + 2 * lr);
        qa[mt][0] = pkh(qv0.x * QS, qv0.y * QS);   // row lq,   k 2lr..
        qa[mt][1] = pkh(qv2.x * QS, qv2.y * QS);   // row lq+8, k 2lr..
        qa[mt][2] = pkh(qv1.x * QS, qv1.y * QS);   // row lq,   k 8+2lr..
        qa[mt][3] = pkh(qv3.x * QS, qv3.y * QS);   // row lq+8, k 8+2lr..
        ib[mt] = ds9(r0) + 21 - 2 * lr;
#pragma unroll
        for (int nt = 0; nt < 2; ++nt)
#pragma unroll
            for (int j = 0; j < 4; ++j) o[mt][nt][j] = 0.f;
#pragma unroll
        for (int j = 0; j < 4; ++j) oS[mt][j] = 0.f;
    }

    for (int r = 0; r < 4; ++r) {
        unsigned b0[4], bp[4], bm[4];
#pragma unroll
        for (int mt = 0; mt < 4; ++mt) {
            uint4 bq = sQ[ib[mt] - 2 * r];   // {B[i0], B[i0+1], B[i0-1], -}
            b0[mt] = bq.x; bp[mt] = bq.y; bm[mt] = bq.z;
        }
        const unsigned* kbase = sK + r * 128 + lane * 2;
        const unsigned* vbase = sV + r * 128 + lane * 2;

#pragma unroll
        for (int qq = 0; qq < 8; ++qq) {
            uint2 k0 = *(const uint2*)(kbase + qq * 512);
            uint2 k1 = *(const uint2*)(kbase + qq * 512 + 64);
            uint2 v0 = *(const uint2*)(vbase + qq * 512);
            uint2 v1 = *(const uint2*)(vbase + qq * 512 + 64);

#pragma unroll
            for (int mt = 0; mt < 4; ++mt) {
                unsigned e0, e1, f0, f1;
                // ntile0: C-init {B[i0], B[i0+1]}  (rows lq / lq+8)
                mma_f16h(e0, e1, qa[mt][0], qa[mt][1], qa[mt][2], qa[mt][3],
                         k0.x, k0.y, b0[mt], bp[mt]);
                // ntile1: cols+8 -> ds+1 -> C-init {B[i0-1], B[i0]}
                mma_f16h(f0, f1, qa[mt][0], qa[mt][1], qa[mt][2], qa[mt][3],
                         k1.x, k1.y, bm[mt], b0[mt]);

                unsigned a0 = hex2(e0);   // row lq,   keys 2lr,2lr+1
                unsigned a1 = hex2(e1);   // row lq+8, keys 2lr,2lr+1
                unsigned a2 = hex2(f0);   // row lq,   keys 8+2lr..
                unsigned a3 = hex2(f1);   // row lq+8, keys 8+2lr..

                mma_f16(o[mt][0][0], o[mt][0][1], o[mt][0][2], o[mt][0][3],
                        a0, a1, a2, a3, v0.x, v0.y);
                mma_f16(o[mt][1][0], o[mt][1][1], o[mt][1][2], o[mt][1][3],
                        a0, a1, a2, a3, v1.x, v1.y);
                mma_f16(oS[mt][0], oS[mt][1], oS[mt][2], oS[mt][3],
                        a0, a1, a2, a3, bsum, bsum);

                if (qq < 7) {   // slide bias window: i0 -> i0-1
                    bp[mt] = b0[mt];
                    b0[mt] = bm[mt];
                    bm[mt] = sB[ib[mt] - 2 * r - qq - 2];
                }
            }
        }
    }
}

// ---------------------------------------------------------------------------
// Fully fused kernel: one CTA per (b,head).
// ---------------------------------------------------------------------------
__global__ __launch_bounds__(256, 2) void fused_kernel(
    const float* __restrict__ qkv, const float* __restrict__ grid,
    const float* __restrict__ W0, const float* __restrict__ B0,
    const float* __restrict__ G1, const float* __restrict__ Be1,
    const float* __restrict__ W1, const float* __restrict__ B1,
    const float* __restrict__ G2, const float* __restrict__ Be2,
    const float* __restrict__ W2, const float* __restrict__ B2,
    const float* __restrict__ G3, const float* __restrict__ Be3,
    const float* __restrict__ W3, const float* __restrict__ B3,
    float* __restrict__ out)
{
    extern __shared__ float sm[];
    unsigned* sK1 = (unsigned*)(sm + SK1);
    unsigned* sV1 = (unsigned*)(sm + SV1);
    unsigned* sK2 = (unsigned*)(sm + SK2);
    unsigned* sV2 = (unsigned*)(sm + SV2);
    float* sPos1 = sm + SP1;
    float* sPos2 = sm + SP2;
    unsigned* sB1 = (unsigned*)(sm + SB1);
    unsigned* sB2 = (unsigned*)(sm + SB2);
    uint4* sQ1 = (uint4*)(sm + SQ1);
    uint4* sQ2 = (uint4*)(sm + SQ2);

    int bh = blockIdx.x;
    int b = bh / NHEAD, h = bh % NHEAD;
    const float* qkvB = qkv + (long)b * NTOK * 288;
    const float* gridB = grid + (long)b * NTOK * 96;

    int tid = threadIdx.x;

    // ---- stage K1 (qkv.k), K2 (grid) as fp16 K-B-frags; V1 (qkv.v) as fp16 V-B-frags
    for (int e = tid; e < NTOK * 4; e += 256) {
        int key = e >> 2;
        int c4 = (e & 3) * 4;
        float4 kv = *(const float4*)(qkvB + key * 288 + 96 + h * 16 + c4);
        float4 vv = *(const float4*)(qkvB + key * 288 + 192 + h * 16 + c4);
        float4 gv = *(const float4*)(gridB + key * 96 + h * 16 + c4);
        float kj[4] = { kv.x, kv.y, kv.z, kv.w };
        float vj[4] = { vv.x, vv.y, vv.z, vv.w };
        float gj[4] = { gv.x, gv.y, gv.z, gv.w };
        int blk = key >> 4, kl = key & 15;
        int ntK = kl >> 3, lqK = kl & 7;
        // K/G: two f16x2 words (dims c4..c4+1, c4+2..c4+3)
#pragma unroll
        for (int jp = 0; jp < 2; ++jp) {
            int d = c4 + 2 * jp;
            int w = (blk * 2 + ntK) * 64 + lqK * 8 + ((d & 7) >> 1) * 2 + (d >> 3);
            sK1[w] = pkh(kj[2 * jp], kj[2 * jp + 1]);
            sK2[w] = pkh(gj[2 * jp], gj[2 * jp + 1]);
        }
        // V: 4 half stores
        int lrV = (kl & 7) >> 1, regV = kl >> 3, hfV = kl & 1;
#pragma unroll
        for (int j = 0; j < 4; ++j) {
            int dim = c4 + j;
            int w = (blk * 2 + (dim >> 3)) * 64 + (dim & 7) * 8 + lrV * 2 + regV;
            ((__half*)sV1)[w * 2 + hfV] = __float2half_rn(vj[j]);
        }
    }

    // ---- inline pos-MLP: threads 0..85 compute the two 43-row tables ----
    if (tid < 86) {
        int i = (tid >= NPOS) ? 1 : 0;
        int m = tid - i * NPOS;
        float bh_ = -7.f;
        float bw_ = (float)(m / 15) - 7.f;
        float bd_ = (float)(m % 15) - 7.f;
        float x[6], y[6];
#pragma unroll
        for (int j = 0; j < 6; ++j) {
            const float* w = W0 + (i * 6 + j) * 3;
            x[j] = bh_ * w[0] + bw_ * w[1] + bd_ * w[2] + B0[i * 6 + j];
        }
        {
            float mu = 0.f;
#pragma unroll
            for (int j = 0; j < 6; ++j) mu += x[j];
            mu *= (1.f / 6.f);
            float var = 0.f;
#pragma unroll
            for (int j = 0; j < 6; ++j) { float d = x[j] - mu; var += d * d; }
            float inv = rsqrtf(var * (1.f / 6.f) + 1e-5f);
#pragma unroll
            for (int j = 0; j < 6; ++j)
                x[j] = fmaxf((x[j] - mu) * inv * G1[i * 6 + j] + Be1[i * 6 + j], 0.f);
#pragma unroll
            for (int j = 0; j < 6; ++j) {
                const float* w = W1 + (i * 6 + j) * 6;
                float s = B1[i * 6 + j];
#pragma unroll
                for (int k = 0; k < 6; ++k) s += x[k] * w[k];
                y[j] = s;
            }
        }
        {
            float mu = 0.f;
#pragma unroll
            for (int j = 0; j < 6; ++j) mu += y[j];
            mu *= (1.f / 6.f);
            float var = 0.f;
#pragma unroll
            for (int j = 0; j < 6; ++j) { float d = y[j] - mu; var += d * d; }
            float inv = rsqrtf(var * (1.f / 6.f) + 1e-5f);
#pragma unroll
            for (int j = 0; j < 6; ++j)
                y[j] = fmaxf((y[j] - mu) * inv * G2[i * 6 + j] + Be2[i * 6 + j], 0.f);
#pragma unroll
            for (int j = 0; j < 6; ++j) {
                const float* w = W2 + (i * 6 + j) * 6;
                float s = B2[i * 6 + j];
#pragma unroll
                for (int k = 0; k < 6; ++k) s += y[k] * w[k];
                x[j] = s;
            }
        }
        {
            float mu = 0.f;
#pragma unroll
            for (int j = 0; j < 6; ++j) mu += x[j];
            mu *= (1.f / 6.f);
            float var = 0.f;
#pragma unroll
            for (int j = 0; j < 6; ++j) { float d = x[j] - mu; var += d * d; }
            float inv = rsqrtf(var * (1.f / 6.f) + 1e-5f);
#pragma unroll
            for (int j = 0; j < 6; ++j)
                x[j] = fmaxf((x[j] - mu) * inv * G3[i * 6 + j] + Be3[i * 6 + j], 0.f);
            const float* w = W3 + (i * NHEAD + h) * 6;
            float s = B3[i * NHEAD + h];
#pragma unroll
            for (int k = 0; k < 6; ++k) s += x[k] * w[k];
            ((i == 0) ? sPos1 : sPos2)[m] = s * L2E;
        }
    }
    __syncthreads();

    // ---- build packed bias-pair tables: sB[i] = (sPos[i], sPos[i-1]) as f16x2
    if (tid < 96) {
        int i = (tid >= 48) ? 1 : 0;
        int m = tid - i * 48;
        const float* sp = i ? sPos2 : sPos1;
        float lo = (m < NPOS) ? sp[m] : 0.f;
        float hi = (m >= 1 && m - 1 < NPOS) ? sp[m - 1] : 0.f;
        ((i == 0) ? sB1 : sB2)[m] = pkh(lo, hi);
    }
    __syncthreads();

    // ---- build bias-quad tables: sQ[i] = {sB[i], sB[i+1], sB[i-1], 0}
    if (tid < 96) {
        int i = (tid >= 48) ? 1 : 0;
        int m = tid - i * 48;
        const unsigned* sb = i ? sB2 : sB1;
        uint4 q;
        q.x = sb[m];
        q.y = (m < 47) ? sb[m + 1] : 0u;
        q.z = (m >= 1) ? sb[m - 1] : 0u;
        q.w = 0u;
        ((i == 0) ? sQ1 : sQ2)[m] = q;
    }
    __syncthreads();

    int warp = tid >> 5, lane = tid & 31, lq = lane >> 2, lr = lane & 3;
    float o[4][2][4], oS[4][4];

    // ================= PASS 1: Q=grid, K=qkv.k, V=qkv.v =================
    attn_core(gridB + h * 16, 96, sK1, sV1, sQ1, sB1, warp, lane, o, oS);

    // normalize; write x1 into sV2 (fp16 V-B-frag layout; rows become keys)
#pragma unroll
    for (int mt = 0; mt < 4; ++mt) {
        float sl = __shfl_sync(0xffffffffu, oS[mt][0], lane & ~3);
        float sh = __shfl_sync(0xffffffffu, oS[mt][2], lane & ~3);
        float il = 1.f / sl, ih = 1.f / sh;
        int r0 = warp * 64 + mt * 16 + lq;
#pragma unroll
        for (int nt = 0; nt < 2; ++nt) {
#pragma unroll
            for (int j = 0; j < 4; ++j) {
                float val = o[mt][nt][j] * ((j < 2) ? il : ih);
                int row = (j < 2) ? r0 : (r0 + 8);
                int col = nt * 8 + 2 * lr + (j & 1);
                int kb = row & 15;
                int w = ((row >> 4) * 2 + nt) * 64 + (col & 7) * 8 + ((kb & 7) >> 1) * 2 + (kb >> 3);
                ((__half*)sV2)[w * 2 + (kb & 1)] = __float2half_rn(val);
            }
        }
    }
    __syncthreads();

    // ================= PASS 2: Q=qkv.q, K=grid, V=x1 =================
    attn_core(qkvB + h * 16, 288, sK2, sV2, sQ2, sB2, warp, lane, o, oS);

    float* O = out + (long)b * NTOK * 96 + h * 16;
#pragma unroll
    for (int mt = 0; mt < 4; ++mt) {
        float sl = __shfl_sync(0xffffffffu, oS[mt][0], lane & ~3);
        float sh = __shfl_sync(0xffffffffu, oS[mt][2], lane & ~3);
        float il = 1.f / sl, ih = 1.f / sh;
        int r0 = warp * 64 + mt * 16 + lq, r1 = r0 + 8;
#pragma unroll
        for (int nt = 0; nt < 2; ++nt) {
            int col = nt * 8 + 2 * lr;
            *(float2*)(O + r0 * 96 + col) = make_float2(o[mt][nt][0] * il, o[mt][nt][1] * il);
            *(float2*)(O + r1 * 96 + col) = make_float2(o[mt][nt][2] * ih, o[mt][nt][3] * ih);
        }
    }
}

// ---------------------------------------------------------------------------
extern "C" void kernel_launch(void* const* d_in, const int* in_sizes, int n_in,
                              void* d_out, int out_size)
{
    const float* qkv  = (const float*)d_in[0];
    const float* grid = (const float*)d_in[1];
    const float* W0  = (const float*)d_in[2];
    const float* B0  = (const float*)d_in[3];
    const float* G1  = (const float*)d_in[4];
    const float* Be1 = (const float*)d_in[5];
    const float* W1  = (const float*)d_in[6];
    const float* B1  = (const float*)d_in[7];
    const float* G2  = (const float*)d_in[8];
    const float* Be2 = (const float*)d_in[9];
    const float* W2  = (const float*)d_in[10];
    const float* B2  = (const float*)d_in[11];
    const float* G3  = (const float*)d_in[12];
    const float* Be3 = (const float*)d_in[13];
    const float* W3  = (const float*)d_in[14];
    const float* B3  = (const float*)d_in[15];
    float* out = (float*)d_out;

    const int SMEM = SMEM_WORDS * sizeof(float);   // ~67.8 KB -> 2 CTA/SM
    cudaFuncSetAttribute(fused_kernel, cudaFuncAttributeMaxDynamicSharedMemorySize, SMEM);

    fused_kernel<<<NB * NHEAD, 256, SMEM>>>(
        qkv, grid, W0, B0, G1, Be1, W1, B1, G2, Be2, W2, B2, G3, Be3, W3, B3, out);
}